// round 2
// baseline (speedup 1.0000x reference)
#include <cuda_runtime.h>
#include <cstdint>

#define BATCH 8192
#define DCONT 1024
#define VCAT  10000
#define VEC   2500          // float4s per categorical row
#define FULL  0xffffffffu

// Accumulate one W_cat row (16 floats = 4 float4) into the per-lane accumulator.
#define ADDROW(col)                                                         \
    do {                                                                    \
        const float4* _w = Wcat4 + (size_t)(col) * 4;                       \
        float4 _w0 = __ldg(_w + 0), _w1 = __ldg(_w + 1);                    \
        float4 _w2 = __ldg(_w + 2), _w3 = __ldg(_w + 3);                    \
        a0.x += _w0.x; a0.y += _w0.y; a0.z += _w0.z; a0.w += _w0.w;         \
        a1.x += _w1.x; a1.y += _w1.y; a1.z += _w1.z; a1.w += _w1.w;         \
        a2.x += _w2.x; a2.y += _w2.y; a2.z += _w2.z; a2.w += _w2.w;         \
        a3.x += _w3.x; a3.y += _w3.y; a3.z += _w3.z; a3.w += _w3.w;         \
        cnt++;                                                              \
    } while (0)

__global__ void __launch_bounds__(128, 8)
spfl_kernel(const float* __restrict__ xcont,
            const float* __restrict__ xcat,
            const float* __restrict__ Wc,
            const float* __restrict__ Wcat,
            const float* __restrict__ bias,
            float* __restrict__ out) {
    int warp = (blockIdx.x * blockDim.x + threadIdx.x) >> 5;
    int lane = threadIdx.x & 31;
    if (warp >= BATCH) return;
    const int row = warp;

    const float4* __restrict__ xr    = reinterpret_cast<const float4*>(xcat) + (size_t)row * VEC;
    const float4* __restrict__ Wcat4 = reinterpret_cast<const float4*>(Wcat);
    const float4* __restrict__ Wc4   = reinterpret_cast<const float4*>(Wc);

    // Per-lane full 16-output accumulator
    float4 a0 = make_float4(0.f,0.f,0.f,0.f);
    float4 a1 = make_float4(0.f,0.f,0.f,0.f);
    float4 a2 = make_float4(0.f,0.f,0.f,0.f);
    float4 a3 = make_float4(0.f,0.f,0.f,0.f);
    int cnt = 0;

    // ---- categorical branch: stream mask with 8 loads in flight per lane ----
    for (int i0 = 0; i0 < VEC; i0 += 256) {
        float4 v[8];
        #pragma unroll
        for (int j = 0; j < 8; j++) {
            int idx = i0 + j * 32 + lane;
            v[j] = (idx < VEC) ? __ldg(xr + idx) : make_float4(0.f,0.f,0.f,0.f);
        }
        #pragma unroll
        for (int j = 0; j < 8; j++) {
            float4 vv = v[j];
            if (vv.x != 0.f || vv.y != 0.f || vv.z != 0.f || vv.w != 0.f) {
                int base = (i0 + j * 32 + lane) * 4;   // scalar vocab column of vv.x
                if (vv.x != 0.f) ADDROW(base + 0);
                if (vv.y != 0.f) ADDROW(base + 1);
                if (vv.z != 0.f) ADDROW(base + 2);
                if (vv.w != 0.f) ADDROW(base + 3);
            }
        }
    }

    // ---- continuous branch: lane owns feature jb+lane, W loads are L1-resident ----
    const float* __restrict__ xc = xcont + (size_t)row * DCONT;
    #pragma unroll 2
    for (int jb = 0; jb < DCONT; jb += 32) {
        float x = __ldg(xc + jb + lane);
        const float4* w = Wc4 + (size_t)(jb + lane) * 4;
        float4 w0 = __ldg(w + 0), w1 = __ldg(w + 1);
        float4 w2 = __ldg(w + 2), w3 = __ldg(w + 3);
        a0.x += x * w0.x; a0.y += x * w0.y; a0.z += x * w0.z; a0.w += x * w0.w;
        a1.x += x * w1.x; a1.y += x * w1.y; a1.z += x * w1.z; a1.w += x * w1.w;
        a2.x += x * w2.x; a2.y += x * w2.y; a2.z += x * w2.z; a2.w += x * w2.w;
        a3.x += x * w3.x; a3.y += x * w3.y; a3.z += x * w3.z; a3.w += x * w3.w;
    }

    // ---- warp reduction: every lane ends with the full 16-output row sum ----
    #pragma unroll
    for (int off = 16; off >= 1; off >>= 1) {
        a0.x += __shfl_xor_sync(FULL, a0.x, off);
        a0.y += __shfl_xor_sync(FULL, a0.y, off);
        a0.z += __shfl_xor_sync(FULL, a0.z, off);
        a0.w += __shfl_xor_sync(FULL, a0.w, off);
        a1.x += __shfl_xor_sync(FULL, a1.x, off);
        a1.y += __shfl_xor_sync(FULL, a1.y, off);
        a1.z += __shfl_xor_sync(FULL, a1.z, off);
        a1.w += __shfl_xor_sync(FULL, a1.w, off);
        a2.x += __shfl_xor_sync(FULL, a2.x, off);
        a2.y += __shfl_xor_sync(FULL, a2.y, off);
        a2.z += __shfl_xor_sync(FULL, a2.z, off);
        a2.w += __shfl_xor_sync(FULL, a2.w, off);
        a3.x += __shfl_xor_sync(FULL, a3.x, off);
        a3.y += __shfl_xor_sync(FULL, a3.y, off);
        a3.z += __shfl_xor_sync(FULL, a3.z, off);
        a3.w += __shfl_xor_sync(FULL, a3.w, off);
        cnt  += __shfl_xor_sync(FULL, cnt, off);
    }

    // ---- lanes 0-3 write one float4 quarter each ----
    if (lane < 4) {
        float4 q = (lane == 0) ? a0 : (lane == 1) ? a1 : (lane == 2) ? a2 : a3;
        float4 b4 = __ldg(reinterpret_cast<const float4*>(bias) + lane);
        float f = (float)(DCONT + cnt);
        q.x += f * b4.x; q.y += f * b4.y; q.z += f * b4.z; q.w += f * b4.w;
        reinterpret_cast<float4*>(out)[(size_t)row * 4 + lane] = q;
    }
}

extern "C" void kernel_launch(void* const* d_in, const int* in_sizes, int n_in,
                              void* d_out, int out_size) {
    const float* xcont = (const float*)d_in[0];   // [8192, 1024]
    const float* xcat  = (const float*)d_in[1];   // [8192, 10000]
    const float* Wc    = (const float*)d_in[2];   // [1024, 16]
    const float* Wcat  = (const float*)d_in[3];   // [10000, 16]
    const float* bias  = (const float*)d_in[4];   // [16]
    float* out = (float*)d_out;                   // [8192, 16]

    // 1 row per warp, 4 warps per block -> 2048 blocks
    dim3 grid(BATCH / 4);
    dim3 block(128);
    spfl_kernel<<<grid, block>>>(xcont, xcat, Wc, Wcat, bias, out);
}

// round 3
// speedup vs baseline: 1.1582x; 1.1582x over previous
#include <cuda_runtime.h>
#include <cstdint>

#define BATCH 8192
#define DCONT 1024
#define VCAT  10000
#define VEC   2500          // float4s per categorical row
#define FULL  0xffffffffu

__global__ void __launch_bounds__(128, 10)
spfl_kernel(const float* __restrict__ xcont,
            const float* __restrict__ xcat,
            const float* __restrict__ Wc,
            const float* __restrict__ Wcat,
            const float* __restrict__ bias,
            float* __restrict__ out) {
    const int warp = (blockIdx.x * blockDim.x + threadIdx.x) >> 5;
    const int lane = threadIdx.x & 31;
    if (warp >= BATCH) return;
    const int row = warp;
    const int g = lane >> 2;
    const int c = lane & 3;

    const uint4*  __restrict__ xr    = reinterpret_cast<const uint4*>(xcat) + (size_t)row * VEC;
    const float4* __restrict__ Wcat4 = reinterpret_cast<const float4*>(Wcat);
    const float4* __restrict__ Wc4   = reinterpret_cast<const float4*>(Wc);

    // Each lane accumulates one float4 quarter (c) of the 16 outputs; g-partials
    // are reduced at the end. Cat gathers land only in g==0 lanes.
    float4 acc = make_float4(0.f, 0.f, 0.f, 0.f);
    int cnt = 0;

    // ---- categorical branch: stream 0/1 mask, 8 LDG.128 in flight per lane ----
    for (int i0 = 0; i0 < VEC; i0 += 256) {
        uint4 v[8];
        #pragma unroll
        for (int j = 0; j < 8; j++) {
            int idx = i0 + j * 32 + lane;
            v[j] = (idx < VEC) ? __ldg(xr + idx) : make_uint4(0u, 0u, 0u, 0u);
        }
        #pragma unroll
        for (int j = 0; j < 8; j++) {
            // 4-bit nonzero mask for this lane's float4 (mask values are 0.0/1.0)
            unsigned m4 = (v[j].x ? 1u : 0u) | (v[j].y ? 2u : 0u)
                        | (v[j].z ? 4u : 0u) | (v[j].w ? 8u : 0u);
            cnt += __popc(m4);
            unsigned bal = __ballot_sync(FULL, m4 != 0u);
            while (bal) {                       // rare: E[active] ~ 0.26 per ballot
                int src = __ffs(bal) - 1;
                bal &= bal - 1;
                unsigned sm4 = __shfl_sync(FULL, m4, src);
                int scol = (i0 + j * 32 + src) * 4;   // vocab column of src's v.x
                if (lane < 4) {                 // 4 lanes x 16B = 64B -> 1 wavefront
                    if (sm4 & 1u) { float4 w = __ldg(Wcat4 + (size_t)(scol + 0) * 4 + c);
                        acc.x += w.x; acc.y += w.y; acc.z += w.z; acc.w += w.w; }
                    if (sm4 & 2u) { float4 w = __ldg(Wcat4 + (size_t)(scol + 1) * 4 + c);
                        acc.x += w.x; acc.y += w.y; acc.z += w.z; acc.w += w.w; }
                    if (sm4 & 4u) { float4 w = __ldg(Wcat4 + (size_t)(scol + 2) * 4 + c);
                        acc.x += w.x; acc.y += w.y; acc.z += w.z; acc.w += w.w; }
                    if (sm4 & 8u) { float4 w = __ldg(Wcat4 + (size_t)(scol + 3) * 4 + c);
                        acc.x += w.x; acc.y += w.y; acc.z += w.z; acc.w += w.w; }
                }
            }
        }
    }

    // ---- continuous branch: c/g layout, each LDG.128 covers 512B contiguous ----
    const float* __restrict__ xc = xcont + (size_t)row * DCONT;
    for (int jb = 0; jb < DCONT; jb += 32) {
        float x = __ldg(xc + jb + lane);
        #pragma unroll
        for (int s = 0; s < 4; s++) {
            int jl = s * 8 + g;                         // feature within this block
            float4 w = __ldg(Wc4 + (size_t)(jb + jl) * 4 + c);
            float a = __shfl_sync(FULL, x, jl);
            acc.x += a * w.x; acc.y += a * w.y; acc.z += a * w.z; acc.w += a * w.w;
        }
    }

    // ---- reductions: acc over g (offsets 4,8,16); cnt over all lanes ----
    #pragma unroll
    for (int off = 4; off <= 16; off <<= 1) {
        acc.x += __shfl_xor_sync(FULL, acc.x, off);
        acc.y += __shfl_xor_sync(FULL, acc.y, off);
        acc.z += __shfl_xor_sync(FULL, acc.z, off);
        acc.w += __shfl_xor_sync(FULL, acc.w, off);
    }
    #pragma unroll
    for (int off = 1; off <= 16; off <<= 1)
        cnt += __shfl_xor_sync(FULL, cnt, off);

    if (lane < 4) {   // g == 0, quarter c == lane
        float4 b4 = __ldg(reinterpret_cast<const float4*>(bias) + lane);
        float f = (float)(DCONT + cnt);
        acc.x += f * b4.x; acc.y += f * b4.y;
        acc.z += f * b4.z; acc.w += f * b4.w;
        reinterpret_cast<float4*>(out)[(size_t)row * 4 + lane] = acc;
    }
}

extern "C" void kernel_launch(void* const* d_in, const int* in_sizes, int n_in,
                              void* d_out, int out_size) {
    const float* xcont = (const float*)d_in[0];   // [8192, 1024]
    const float* xcat  = (const float*)d_in[1];   // [8192, 10000]
    const float* Wc    = (const float*)d_in[2];   // [1024, 16]
    const float* Wcat  = (const float*)d_in[3];   // [10000, 16]
    const float* bias  = (const float*)d_in[4];   // [16]
    float* out = (float*)d_out;                   // [8192, 16]

    // 1 row per warp, 4 warps per block -> 2048 blocks
    dim3 grid(BATCH / 4);
    dim3 block(128);
    spfl_kernel<<<grid, block>>>(xcont, xcat, Wc, Wcat, bias, out);
}